// round 9
// baseline (speedup 1.0000x reference)
#include <cuda_runtime.h>
#include <cstdint>
#include <cstddef>

typedef unsigned long long ull;

#define S_LEN    2048
#define BATCH    32
#define HID      256
#define CLUSTER  8
#define N_CLUST  16
#define GRID_REC (CLUSTER * N_CLUST)   // 128

// ---------------- device scratch (no allocations allowed) ----------------
__device__ float g_Xc[(size_t)65536 * 1024];   // [s][b][col] : 256 MB, x@Wx + b

// ---------------- activations (accurate fast paths) ----------------
__device__ __forceinline__ float fsigm(float x) {
    return 1.0f / (1.0f + __expf(-x));
}
__device__ __forceinline__ float ftanh(float x) {
    x = fminf(9.0f, fmaxf(-9.0f, x));
    float e = __expf(-2.0f * x);
    return __fdividef(1.0f - e, 1.0f + e);
}

// ---------------- packed fp32x2 helpers ----------------
__device__ __forceinline__ ull ffma2(ull a, ull b, ull c) {
    ull d;
    asm("fma.rn.f32x2 %0, %1, %2, %3;" : "=l"(d) : "l"(a), "l"(b), "l"(c));
    return d;
}
__device__ __forceinline__ float f2sum(ull v) {
    float lo = __uint_as_float((unsigned)(v & 0xffffffffull));
    float hi = __uint_as_float((unsigned)(v >> 32));
    return lo + hi;
}
__device__ __forceinline__ ull fpack(float lo, float hi) {
    return ((ull)__float_as_uint(hi) << 32) | (ull)__float_as_uint(lo);
}

// ---------------- phase 1: Xc[s][b][col] = x[b][s][:] @ W[:256][col] + bias[col] ----------------
// M = 65536 rows ordered r = s*32 + b ; N = 1024 ; K = 256
__global__ void __launch_bounds__(256, 2) gemm_x_kernel(const float* __restrict__ x,
                                                        const float* __restrict__ W,
                                                        const float* __restrict__ bias) {
    __shared__ float As[8][132];   // k-major, padded (conflict-free)
    __shared__ float Bs[8][128];
    const int tid = threadIdx.x;
    const int rt = blockIdx.x, ct = blockIdx.y;

    const int a_ri = tid >> 1, a_kq = (tid & 1) << 2;
    const int row  = rt * 128 + a_ri;            // r = s*32 + b
    const float* a_src = x + (size_t)(row & 31) * (S_LEN * 256)
                           + (size_t)(row >> 5) * 256 + a_kq;
    const int b_kr = tid >> 5, b_c4 = (tid & 31) << 2;
    const float* b_src = W + (size_t)b_kr * 1024 + ct * 128 + b_c4;

    const int ry = tid >> 4, cx = tid & 15;
    float acc[8][8];
#pragma unroll
    for (int i = 0; i < 8; i++)
#pragma unroll
        for (int j = 0; j < 8; j++) acc[i][j] = 0.0f;

    for (int kb = 0; kb < 256; kb += 8) {
        float4 av = *(const float4*)(a_src + kb);
        float4 bv = *(const float4*)(b_src + (size_t)kb * 1024);
        __syncthreads();
        As[a_kq + 0][a_ri] = av.x;
        As[a_kq + 1][a_ri] = av.y;
        As[a_kq + 2][a_ri] = av.z;
        As[a_kq + 3][a_ri] = av.w;
        *(float4*)&Bs[b_kr][b_c4] = bv;
        __syncthreads();
#pragma unroll
        for (int k = 0; k < 8; k++) {
            float ar[8], br[8];
            *(float4*)(ar)     = *(const float4*)&As[k][ry * 8];
            *(float4*)(ar + 4) = *(const float4*)&As[k][ry * 8 + 4];
            *(float4*)(br)     = *(const float4*)&Bs[k][cx * 8];
            *(float4*)(br + 4) = *(const float4*)&Bs[k][cx * 8 + 4];
#pragma unroll
            for (int i = 0; i < 8; i++)
#pragma unroll
                for (int j = 0; j < 8; j++)
                    acc[i][j] = fmaf(ar[i], br[j], acc[i][j]);
        }
    }

    float bb[8];
#pragma unroll
    for (int j = 0; j < 8; j++) bb[j] = bias[ct * 128 + cx * 8 + j];

    // coalesced epilogue: [s][b][col] layout -> row-major [r][col], float4 stores
#pragma unroll
    for (int i = 0; i < 8; i++) {
        int r = rt * 128 + ry * 8 + i;
        float* dst = g_Xc + (size_t)r * 1024 + ct * 128 + cx * 8;
        float4 v0, v1;
        v0.x = acc[i][0] + bb[0]; v0.y = acc[i][1] + bb[1];
        v0.z = acc[i][2] + bb[2]; v0.w = acc[i][3] + bb[3];
        v1.x = acc[i][4] + bb[4]; v1.y = acc[i][5] + bb[5];
        v1.z = acc[i][6] + bb[6]; v1.w = acc[i][7] + bb[7];
        *(float4*)dst = v0;
        *(float4*)(dst + 4) = v1;
    }
}

// ---------------- init: zero the two tail tensors of the output ----------------
__global__ void init_kernel(float* __restrict__ out) {
    int t = blockIdx.x * blockDim.x + threadIdx.x;   // 4096 threads
    float* tail = out + (size_t)BATCH * S_LEN * HID;
    for (int idx = t; idx < 2 * BATCH * HID; idx += 4096) tail[idx] = 0.0f;
}

// ---------------- phase 2: cluster-local recurrence (mbarrier sync) ----------------
// 16 clusters x 8 CTAs. Cluster cl owns batches {2cl, 2cl+1}. CTA rank owns
// hidden units n in [32*rank, 32*rank+32) -> 128 gate-cols, Wh REGISTER-resident.
// h in smem (double buffered); new h pushed via packed DSMEM u64 stores; per-step
// sync = 8 remote mbarrier arrives + try_wait (no cluster.sync, no L1 flush).
__global__ void __launch_bounds__(256, 1) __cluster_dims__(CLUSTER, 1, 1)
lstm_rec_kernel(const float* __restrict__ W,
                const float* __restrict__ h0,
                const float* __restrict__ c0,
                float* __restrict__ out) {
    __shared__ __align__(16) ull h2s[2][128][2];   // [buf][k2][b] : 4 KB
    __shared__ float red[2][2][128];               // [kh][bl][c]  : 2 KB, conflict-free
    __shared__ __align__(8) ull mbar_s;            // cluster mbarrier (8 arrives/phase)

    const int tid  = threadIdx.x;
    const int cb   = blockIdx.x;
    const int rank = cb & (CLUSTER - 1);
    const int cl   = cb >> 3;
    const int b0g  = cl * 2;                       // first global batch of this cluster

    // ---- dot mapping: c = local col (0..127), kh = k-half (0/1) ----
    const int c   = tid & 127;
    const int kh  = tid >> 7;                      // uniform per warp
    const int g   = c >> 5;
    const int n   = rank * 32 + (c & 31);
    const int colg = g * 256 + n;

    // ---- register-resident Wh slice: 64 k-pairs for (colg, kh) ----
    ull w[64];
#pragma unroll
    for (int j = 0; j < 64; j++) {
        int k = 256 + kh * 128 + 2 * j;
        w[j] = fpack(W[(size_t)k * 1024 + colg],
                     W[(size_t)(k + 1) * 1024 + colg]);
    }

    // ---- owner mapping (gates + c/h update): 64 threads = 32 n x 2 b ----
    const bool owner = (tid < 64);
    const int o_nl = tid & 31;
    const int o_bl = (tid >> 5) & 1;
    const int o_n  = rank * 32 + o_nl;
    const int o_bg = b0g + o_bl;
    float c_reg = owner ? c0[o_bg * HID + o_n] : 0.0f;

    // ---- DSMEM addresses: peer h2s slots + peer mbarriers ----
    uint32_t hbase = (uint32_t)__cvta_generic_to_shared(&h2s[0][0][0]);
    uint32_t mbase = (uint32_t)__cvta_generic_to_shared(&mbar_s);
    uint32_t peer_h[CLUSTER], peer_m[CLUSTER];
    const uint32_t fixed_off =
        (uint32_t)((((rank * 16) + (o_nl >> 1)) * 2 + o_bl) * 8);   // u64 slot (even lanes)
#pragma unroll
    for (int r = 0; r < CLUSTER; r++) {
        uint32_t ra, rm;
        asm("mapa.shared::cluster.u32 %0, %1, %2;" : "=r"(ra) : "r"(hbase), "r"(r));
        asm("mapa.shared::cluster.u32 %0, %1, %2;" : "=r"(rm) : "r"(mbase), "r"(r));
        peer_h[r] = ra + fixed_off;
        peer_m[r] = rm;
    }

    // ---- init: mbarrier (8 arrives per phase) + h buffer 0 ----
    if (tid == 0) {
        asm volatile("mbarrier.init.shared.b64 [%0], %1;" :: "r"(mbase), "r"(CLUSTER) : "memory");
    }
    {
        int k2 = tid >> 1, bb = tid & 1;           // 256 entries, one per thread
        h2s[0][k2][bb] = fpack(h0[(b0g + bb) * HID + 2 * k2],
                               h0[(b0g + bb) * HID + 2 * k2 + 1]);
    }
    __syncthreads();
    // one-time cluster sync: peers' mbarriers + h buffers must exist before use
    asm volatile("barrier.cluster.arrive.aligned;" ::: "memory");
    asm volatile("barrier.cluster.wait.aligned;" ::: "memory");

    // ---- Xc prefetch for step 0 (owners: 4 gate values) ----
    float xc0 = 0.f, xc1 = 0.f, xc2 = 0.f, xc3 = 0.f;
    if (owner) {
        const float* xp = g_Xc + (size_t)o_bg * 1024 + o_n;
        xc0 = xp[0]; xc1 = xp[256]; xc2 = xp[512]; xc3 = xp[768];
    }

    for (int s = 0; s < S_LEN; s++) {
        // ---- dots: 64 k-pairs/thread, weights in regs, h broadcast LDS.128 ----
        const ulonglong2* hptr = (const ulonglong2*)&h2s[s & 1][kh * 64][0];
        ull acc0 = 0ull, acc1 = 0ull;
#pragma unroll
        for (int j = 0; j < 64; j++) {
            ulonglong2 hv = hptr[j];               // [b0 pair, b1 pair] : uniform addr
            acc0 = ffma2(w[j], hv.x, acc0);
            acc1 = ffma2(w[j], hv.y, acc1);
        }
        red[kh][0][c] = f2sum(acc0);               // conflict-free (stride 1 in c)
        red[kh][1][c] = f2sum(acc1);
        __syncthreads();

        // ---- owners: assemble all 4 gates, activations, c/h update, push h ----
        if (owner) {
            float z0 = red[0][o_bl][o_nl]       + red[1][o_bl][o_nl]       + xc0;
            float z1 = red[0][o_bl][32 + o_nl]  + red[1][o_bl][32 + o_nl]  + xc1;
            float z2 = red[0][o_bl][64 + o_nl]  + red[1][o_bl][64 + o_nl]  + xc2;
            float z3 = red[0][o_bl][96 + o_nl]  + red[1][o_bl][96 + o_nl]  + xc3;
            z0 = ftanh(z0); z1 = ftanh(z1); z2 = ftanh(z2); z3 = ftanh(z3);  // quirk: tanh first
            float iv = fsigm(z0);
            float fv = fsigm(z1);
            float gv = ftanh(z2);
            float ov = fsigm(z3);
            c_reg = fv * c_reg + iv * gv;
            float hv = ftanh(c_reg) * ov;

            // pack k-pair (even n = lo, odd n = hi) and push u64 to all 8 CTAs
            float hv_hi = __shfl_xor_sync(0xffffffffu, hv, 1);
            if ((o_nl & 1) == 0) {
                ull hp = fpack(hv, hv_hi);
                uint32_t boff = (uint32_t)(((s & 1) ^ 1) * sizeof(h2s[0]));
#pragma unroll
                for (int r = 0; r < CLUSTER; r++)
                    asm volatile("st.shared::cluster.u64 [%0], %1;"
                                 :: "r"(peer_h[r] + boff), "l"(hp) : "memory");
            }
            out[(size_t)o_bg * (S_LEN * HID) + (size_t)s * HID + o_n] = hv;
        }
        __syncthreads();                           // all DSMEM pushes issued

        // ---- release: one elected thread arrives on all 8 peers ----
        if (tid == 0) {
            asm volatile("fence.acq_rel.cluster;" ::: "memory");
#pragma unroll
            for (int r = 0; r < CLUSTER; r++)
                asm volatile("mbarrier.arrive.release.cluster.shared::cluster.b64 _, [%0];"
                             :: "r"(peer_m[r]) : "memory");
        }

        // ---- prefetch next step's Xc while waiting ----
        if (owner && s + 1 < S_LEN) {
            const float* xp = g_Xc + (size_t)(s + 1) * 32768 + (size_t)o_bg * 1024 + o_n;
            xc0 = xp[0]; xc1 = xp[256]; xc2 = xp[512]; xc3 = xp[768];
        }

        // ---- wait: phase s completes when all 8 CTAs arrived ----
        {
            unsigned par = (unsigned)(s & 1);
            unsigned done;
            do {
                asm volatile(
                    "{\n\t.reg .pred p;\n\t"
                    "mbarrier.try_wait.parity.acquire.cluster.shared::cta.b64 p, [%1], %2, 0x989680;\n\t"
                    "selp.b32 %0, 1, 0, p;\n\t}"
                    : "=r"(done) : "r"(mbase), "r"(par) : "memory");
            } while (!done);
        }
        __syncthreads();
    }
}

// ---------------- launch ----------------
extern "C" void kernel_launch(void* const* d_in, const int* in_sizes, int n_in,
                              void* d_out, int out_size) {
    const float* x    = (const float*)d_in[0];   // (32,2048,256)
    const float* h0   = (const float*)d_in[1];   // (1,32,256)
    const float* c0   = (const float*)d_in[2];   // (1,32,256)
    const float* W    = (const float*)d_in[3];   // (512,1024)
    const float* bias = (const float*)d_in[4];   // (1024,)
    float* out = (float*)d_out;                  // (32,2048,256) + 2*(1,32,256) zeros

    gemm_x_kernel<<<dim3(512, 8, 1), 256>>>(x, W, bias);
    init_kernel<<<16, 256>>>(out);
    lstm_rec_kernel<<<GRID_REC, 256>>>(W, h0, c0, out);
}